// round 7
// baseline (speedup 1.0000x reference)
#include <cuda_runtime.h>
#include <cstdint>

// ---------------------------------------------------------------------------
// Fused MoE gate via 3xTF32 mma.sync with magnitude-balanced accumulation:
//   x*w = hi*wh + (hi*wl + lo*wh),  error ~2^-22 (fp32-equivalent)
// ALL in-tensor-core accumulate chains are short (<=2 mmas, operands within
// ~2^4 in magnitude). Long-range K accumulation happens in fp32 FADDs:
// per K-stage, per tile:  acc += (tm: 2-mma hi*wh) + (tc: 4-mma corrections).
// Gating fused in the epilogue.
// out (float32): [0..T*8) = topk_idx (as float), [T*8..2T*8) = weights*2.5
// ---------------------------------------------------------------------------

#define KD    4096
#define NE    256
#define BM    128
#define BK    16
#define NS    (KD / BK)          // 256 stages

#define OFF_BIAS   1024
#define OFF_TILE   2048
#define A_SZ       16384         // 8 mblk * 2 ksub * 32 lanes * 8 f32
#define B_SZ       32768         // 32 nblk * 2 ksub * 32 lanes * 4 f32
#define STAGE      (A_SZ + B_SZ) // 49152
#define SCORE_SZ   (128 * 257 * 4)
#define SMEM_TOTAL (OFF_TILE + SCORE_SZ)   // 133632 (stage area: 100352)

__device__ __forceinline__ uint32_t f2tf32(float x) {
    uint32_t r;
    asm("cvt.rna.tf32.f32 %0, %1;" : "=r"(r) : "f"(x));
    return r;
}

__device__ __forceinline__ void mma_acc(float* d, const uint32_t* a,
                                        uint32_t b0, uint32_t b1) {
    asm volatile(
        "mma.sync.aligned.m16n8k8.row.col.f32.tf32.tf32.f32 "
        "{%0,%1,%2,%3}, {%4,%5,%6,%7}, {%8,%9}, {%0,%1,%2,%3};"
        : "+f"(d[0]), "+f"(d[1]), "+f"(d[2]), "+f"(d[3])
        : "r"(a[0]), "r"(a[1]), "r"(a[2]), "r"(a[3]), "r"(b0), "r"(b1));
}

// d = a*b + 0   (fresh accumulator)
__device__ __forceinline__ void mma_zro(float* d, const uint32_t* a,
                                        uint32_t b0, uint32_t b1) {
    asm volatile(
        "mma.sync.aligned.m16n8k8.row.col.f32.tf32.tf32.f32 "
        "{%0,%1,%2,%3}, {%4,%5,%6,%7}, {%8,%9}, {%10,%11,%12,%13};"
        : "=f"(d[0]), "=f"(d[1]), "=f"(d[2]), "=f"(d[3])
        : "r"(a[0]), "r"(a[1]), "r"(a[2]), "r"(a[3]), "r"(b0), "r"(b1),
          "f"(0.0f), "f"(0.0f), "f"(0.0f), "f"(0.0f));
}

// store one fp32 element of A into fragment-major smem (hi at slot, lo at +4)
__device__ __forceinline__ void storeA(uint32_t* A, int r, int c, float x) {
    uint32_t hi = f2tf32(x);
    uint32_t lo = f2tf32(x - __uint_as_float(hi));
    int mblk = r >> 4, ksub = c >> 3, kk = c & 7;
    int ln = ((r & 7) << 2) | (kk & 3);
    int sl = ((r >> 3) & 1) | ((kk >> 2) << 1);
    uint32_t* p = A + (((mblk * 2 + ksub) * 32 + ln) << 3) + sl;
    p[0] = hi;
    p[4] = lo;
}

__device__ __forceinline__ void storeB(uint32_t* B, int n, int c, float x) {
    uint32_t hi = f2tf32(x);
    uint32_t lo = f2tf32(x - __uint_as_float(hi));
    int nblk = n >> 3, ksub = c >> 3, kk = c & 7;
    int ln = ((n & 7) << 2) | (kk & 3);
    int sl = (kk >> 2) & 1;
    uint32_t* p = B + (((nblk * 2 + ksub) * 32 + ln) << 2) + sl;
    p[0] = hi;
    p[2] = lo;
}

__global__ __launch_bounds__(512, 1)
void moe_kernel(const float* __restrict__ X, const float* __restrict__ W,
                const float* __restrict__ bias, float* __restrict__ out, int T)
{
    extern __shared__ char sm[];
    const int tid = threadIdx.x, wid = tid >> 5, lane = tid & 31;
    const int wm = wid & 3, wn = wid >> 2;          // 4x4 warp grid
    const int m0 = blockIdx.x * BM;

    if (tid < NE) ((float*)(sm + OFF_BIAS))[tid] = bias[tid];

    const int a_row = tid >> 2, a_c0 = (tid & 3) * 4;
    const float* gA  = X + (size_t)(m0 + a_row) * KD + a_c0;
    const int b_row = tid >> 2, b_c0 = (tid & 3) * 4;
    const float* gB0 = W + (size_t)b_row * KD + b_c0;
    const float* gB1 = W + (size_t)(b_row + 128) * KD + b_c0;

    float acc[2][8][4];
#pragma unroll
    for (int i = 0; i < 2; i++)
#pragma unroll
        for (int j = 0; j < 8; j++)
#pragma unroll
            for (int q = 0; q < 4; q++) acc[i][j][q] = 0.0f;

    float4 ra, rb0, rb1;

#define FETCH(s) {                                                    \
        ra  = *(const float4*)(gA  + (s) * BK);                       \
        rb0 = *(const float4*)(gB0 + (s) * BK);                       \
        rb1 = *(const float4*)(gB1 + (s) * BK);                       \
    }

#define STORE(b) {                                                    \
        uint32_t* As = (uint32_t*)(sm + OFF_TILE + (b) * STAGE);      \
        uint32_t* Bs = (uint32_t*)(sm + OFF_TILE + (b) * STAGE + A_SZ);\
        storeA(As, a_row, a_c0 + 0, ra.x);                            \
        storeA(As, a_row, a_c0 + 1, ra.y);                            \
        storeA(As, a_row, a_c0 + 2, ra.z);                            \
        storeA(As, a_row, a_c0 + 3, ra.w);                            \
        storeB(Bs, b_row, b_c0 + 0, rb0.x);                           \
        storeB(Bs, b_row, b_c0 + 1, rb0.y);                           \
        storeB(Bs, b_row, b_c0 + 2, rb0.z);                           \
        storeB(Bs, b_row, b_c0 + 3, rb0.w);                           \
        storeB(Bs, b_row + 128, b_c0 + 0, rb1.x);                     \
        storeB(Bs, b_row + 128, b_c0 + 1, rb1.y);                     \
        storeB(Bs, b_row + 128, b_c0 + 2, rb1.z);                     \
        storeB(Bs, b_row + 128, b_c0 + 3, rb1.w);                     \
    }

    FETCH(0);
    STORE(0);
    __syncthreads();

    int buf = 0;
    for (int s = 0; s < NS; s++) {
        if (s + 1 < NS) FETCH(s + 1);

        {
            const char* base = sm + OFF_TILE + buf * STAGE;
#pragma unroll
            for (int mt = 0; mt < 2; mt++) {
                const int mblk = wm * 2 + mt;
                const uint4* p0 = (const uint4*)(base +
                    ((((mblk * 2 + 0) * 32 + lane)) << 5));
                const uint4* p1 = (const uint4*)(base +
                    ((((mblk * 2 + 1) * 32 + lane)) << 5));
                uint4 vh0 = p0[0], vl0 = p0[1];
                uint4 vh1 = p1[0], vl1 = p1[1];
                uint32_t AH0[4] = {vh0.x, vh0.y, vh0.z, vh0.w};
                uint32_t AL0[4] = {vl0.x, vl0.y, vl0.z, vl0.w};
                uint32_t AH1[4] = {vh1.x, vh1.y, vh1.z, vh1.w};
                uint32_t AL1[4] = {vl1.x, vl1.y, vl1.z, vl1.w};
#pragma unroll
                for (int nt = 0; nt < 8; nt++) {
                    const int nblk = wn * 8 + nt;
                    uint4 b0 = *(const uint4*)(base + A_SZ +
                        ((((nblk * 2 + 0) * 32 + lane)) << 4));
                    uint4 b1 = *(const uint4*)(base + A_SZ +
                        ((((nblk * 2 + 1) * 32 + lane)) << 4));
                    // b*: {b0hi, b1hi, b0lo, b1lo}
                    float tm[4], tc[4];
                    mma_zro(tm, AH0, b0.x, b0.y);   // hi*wh  (ksub0, c=0)
                    mma_acc(tm, AH1, b1.x, b1.y);   // hi*wh  (ksub1)
                    mma_zro(tc, AH0, b0.z, b0.w);   // hi*wl  (c=0)
                    mma_acc(tc, AL0, b0.x, b0.y);   // lo*wh
                    mma_acc(tc, AH1, b1.z, b1.w);   // hi*wl
                    mma_acc(tc, AL1, b1.x, b1.y);   // lo*wh
                    acc[mt][nt][0] += tm[0] + tc[0];
                    acc[mt][nt][1] += tm[1] + tc[1];
                    acc[mt][nt][2] += tm[2] + tc[2];
                    acc[mt][nt][3] += tm[3] + tc[3];
                }
            }
        }

        if (s + 1 < NS) STORE(buf ^ 1);
        __syncthreads();
        buf ^= 1;
    }
#undef FETCH
#undef STORE

    // ---------------- dump logits to smem scores --------------------------
    {
        float* sc = (float*)(sm + OFF_TILE);
#pragma unroll
        for (int mt = 0; mt < 2; mt++) {
            int r = wm * 32 + mt * 16 + (lane >> 2);
#pragma unroll
            for (int nt = 0; nt < 8; nt++) {
                int c = wn * 64 + nt * 8 + (lane & 3) * 2;
                sc[r * 257 + c]           = acc[mt][nt][0];
                sc[r * 257 + c + 1]       = acc[mt][nt][1];
                sc[(r + 8) * 257 + c]     = acc[mt][nt][2];
                sc[(r + 8) * 257 + c + 1] = acc[mt][nt][3];
            }
        }
    }
    __syncthreads();

    // ---------------- fused gating (warps 0-3, one token per thread) ------
    if (wid < 4) {
        const int row = wid * 32 + lane;
        float* srow = (float*)(sm + OFF_TILE) + row * 257;
        const float* bs = (const float*)(sm + OFF_BIAS);

        float gs[8];
#pragma unroll
        for (int g = 0; g < 8; g++) {
            float m1 = -1e30f, m2 = -1e30f;
#pragma unroll
            for (int i = 0; i < 32; i++) {
                float lg = srow[g * 32 + i];
                float scv = 1.0f / (1.0f + expf(-lg));   // sigmoid
                float v = scv + bs[g * 32 + i];          // scores_for_choice
                srow[g * 32 + i] = v;
                if (v > m1) { m2 = m1; m1 = v; }
                else if (v > m2) m2 = v;
            }
            gs[g] = m1 + m2;
        }
        // stable top-4 groups (ties -> lower index)
        int mask = 0;
#pragma unroll
        for (int j = 0; j < 8; j++) {
            int rk = 0;
#pragma unroll
            for (int j2 = 0; j2 < 8; j2++)
                rk += (gs[j2] > gs[j]) || (gs[j2] == gs[j] && j2 < j);
            if (rk < 4) mask |= 1 << j;
        }
        // stable top-8 experts over masked scores (matches lax.top_k ties)
        float bv[8]; int bi[8];
#pragma unroll
        for (int k = 0; k < 8; k++) { bv[k] = -1e30f; bi[k] = 0; }
        for (int e = 0; e < NE; e++) {
            float v = ((mask >> (e >> 5)) & 1) ? srow[e] : 0.0f;
            if (v > bv[7]) {
                bv[7] = v; bi[7] = e;
#pragma unroll
                for (int k = 7; k > 0; k--)
                    if (bv[k] > bv[k - 1]) {
                        float tv = bv[k]; bv[k] = bv[k - 1]; bv[k - 1] = tv;
                        int ti = bi[k];  bi[k] = bi[k - 1]; bi[k - 1] = ti;
                    }
            }
        }
        float ws = 0.0f, wv[8];
#pragma unroll
        for (int k = 0; k < 8; k++) { wv[k] = bv[k] - bs[bi[k]]; ws += wv[k]; }
        const size_t token = (size_t)(m0 + row);
#pragma unroll
        for (int k = 0; k < 8; k++) {
            out[token * 8 + k] = (float)bi[k];
            out[(size_t)T * 8 + token * 8 + k] = wv[k] / (ws + 1e-20f) * 2.5f;
        }
    }
}

extern "C" void kernel_launch(void* const* d_in, const int* in_sizes, int n_in,
                              void* d_out, int out_size)
{
    const float* X    = (const float*)d_in[0];
    const float* W    = (const float*)d_in[1];
    const float* bias = (const float*)d_in[2];
    float* out = (float*)d_out;

    const int T = in_sizes[0] / KD;   // 16384

    cudaFuncSetAttribute(moe_kernel,
                         cudaFuncAttributeMaxDynamicSharedMemorySize, SMEM_TOTAL);
    moe_kernel<<<T / BM, 512, SMEM_TOTAL>>>(X, W, bias, out, T);
}

// round 8
// speedup vs baseline: 1.9431x; 1.9431x over previous
#include <cuda_runtime.h>
#include <cstdint>

// ---------------------------------------------------------------------------
// Fused MoE gate via 3xTF32 mma.sync (R7-proven numerics) with a rebuilt
// data path: W pre-split to (hi,lo) float2 planes in global scratch,
// cp.async 4-stage pipeline, conflict-free padded smem, consumer-side X split.
//   x*w = hi*wh + (hi*wl + lo*wh); chains <=2 (main) / 4 (corr) mmas,
//   long-range K accumulation in fp32 FADDs (magnitude-balanced).
// out (float32): [0..T*8) = topk_idx (as float), [T*8..2T*8) = weights*2.5
// ---------------------------------------------------------------------------

#define KD   4096
#define NE   256
#define BM   128
#define BK   16
#define NS   (KD / BK)            // 256 stages

#define A_PITCH_W 20              // 16 data words + 4 pad  (80 B/row)
#define A_SMEM    (128 * A_PITCH_W * 4)          // 10240 B
#define B_PITCH_W 40              // 16 (hi,lo) pairs = 32 words + 8 pad (160 B)
#define B_SMEM    (256 * B_PITCH_W * 4)          // 40960 B
#define STAGE_SZ  (A_SMEM + B_SMEM)              // 51200 B
#define OFF_BIAS  0
#define OFF_STAGE 1024
#define SMEM_TOTAL (OFF_STAGE + 4 * STAGE_SZ)    // 205824 B

__device__ __align__(16) float2 g_wsplit[(size_t)NE * KD];   // 8 MB scratch

__device__ __forceinline__ uint32_t f2tf32(float x) {
    uint32_t r;
    asm("cvt.rna.tf32.f32 %0, %1;" : "=r"(r) : "f"(x));
    return r;
}
__device__ __forceinline__ uint32_t smem_u32(const void* p) {
    uint32_t a;
    asm("{ .reg .u64 t; cvta.to.shared.u64 t, %1; cvt.u32.u64 %0, t; }"
        : "=r"(a) : "l"(p));
    return a;
}
__device__ __forceinline__ float lds_f32(uint32_t a) {
    float v; asm volatile("ld.shared.f32 %0, [%1];" : "=f"(v) : "r"(a));
    return v;
}
__device__ __forceinline__ void lds_v2(uint32_t a, uint32_t& x, uint32_t& y) {
    asm volatile("ld.shared.v2.u32 {%0,%1}, [%2];" : "=r"(x), "=r"(y) : "r"(a));
}

__device__ __forceinline__ void mma_acc(float* d, const uint32_t* a,
                                        uint32_t b0, uint32_t b1) {
    asm volatile(
        "mma.sync.aligned.m16n8k8.row.col.f32.tf32.tf32.f32 "
        "{%0,%1,%2,%3}, {%4,%5,%6,%7}, {%8,%9}, {%0,%1,%2,%3};"
        : "+f"(d[0]), "+f"(d[1]), "+f"(d[2]), "+f"(d[3])
        : "r"(a[0]), "r"(a[1]), "r"(a[2]), "r"(a[3]), "r"(b0), "r"(b1));
}
__device__ __forceinline__ void mma_zro(float* d, const uint32_t* a,
                                        uint32_t b0, uint32_t b1) {
    asm volatile(
        "mma.sync.aligned.m16n8k8.row.col.f32.tf32.tf32.f32 "
        "{%0,%1,%2,%3}, {%4,%5,%6,%7}, {%8,%9}, {%10,%11,%12,%13};"
        : "=f"(d[0]), "=f"(d[1]), "=f"(d[2]), "=f"(d[3])
        : "r"(a[0]), "r"(a[1]), "r"(a[2]), "r"(a[3]), "r"(b0), "r"(b1),
          "f"(0.0f), "f"(0.0f), "f"(0.0f), "f"(0.0f));
}

// ------------------- pre-kernel: split W into (hi,lo) pairs ----------------
__global__ __launch_bounds__(256)
void wsplit_kernel(const float* __restrict__ W) {
    int i = blockIdx.x * blockDim.x + threadIdx.x;   // 0 .. NE*KD-1
    float w = W[i];
    uint32_t hi = f2tf32(w);
    float res = w - __uint_as_float(hi);
    g_wsplit[i] = make_float2(__uint_as_float(hi),
                              __uint_as_float(f2tf32(res)));
}

// --------------------------- main fused kernel -----------------------------
__global__ __launch_bounds__(512, 1)
void moe_kernel(const float* __restrict__ X, const float* __restrict__ bias,
                float* __restrict__ out, int T)
{
    extern __shared__ char sm[];
    const uint32_t sb = smem_u32(sm);
    const int tid = threadIdx.x, wid = tid >> 5, lane = tid & 31;
    const int wm = wid & 3, wn = wid >> 2;           // 4x4 warp grid
    const int m0 = blockIdx.x * BM;
    const int fr = lane >> 2, fc = lane & 3;

    if (tid < NE) ((float*)(sm + OFF_BIAS))[tid] = bias[tid];

    // cp.async thread mapping (computed once)
    const int a_row = tid >> 2, a_seg = tid & 3;
    const char* a_src = (const char*)(X + (size_t)(m0 + a_row) * KD) + a_seg * 16;
    const uint32_t a_dst = a_row * (A_PITCH_W * 4) + a_seg * 16;

#define ISSUE(s) do {                                                          \
    uint32_t stb_ = sb + OFF_STAGE + ((s) & 3) * STAGE_SZ;                     \
    asm volatile("cp.async.cg.shared.global [%0], [%1], 16;"                   \
                 :: "r"(stb_ + a_dst), "l"(a_src + (size_t)(s) * (BK * 4)));   \
    _Pragma("unroll")                                                          \
    for (int i_ = 0; i_ < 4; i_++) {                                           \
        int id_ = tid + i_ * 512;                                              \
        int br_ = id_ >> 3, bseg_ = id_ & 7;                                   \
        uint32_t bd_ = stb_ + A_SMEM + br_ * (B_PITCH_W * 4) + bseg_ * 16;     \
        const char* bs_ = (const char*)(g_wsplit + (size_t)br_ * KD            \
                                        + (s) * BK) + bseg_ * 16;              \
        asm volatile("cp.async.cg.shared.global [%0], [%1], 16;"               \
                     :: "r"(bd_), "l"(bs_));                                   \
    }                                                                          \
} while (0)

    ISSUE(0); asm volatile("cp.async.commit_group;" ::: "memory");
    ISSUE(1); asm volatile("cp.async.commit_group;" ::: "memory");
    ISSUE(2); asm volatile("cp.async.commit_group;" ::: "memory");

    float acc[2][8][4];
#pragma unroll
    for (int i = 0; i < 2; i++)
#pragma unroll
        for (int j = 0; j < 8; j++)
#pragma unroll
            for (int q = 0; q < 4; q++) acc[i][j][q] = 0.0f;

    for (int s = 0; s < NS; s++) {
        asm volatile("cp.async.wait_group 2;" ::: "memory");
        __syncthreads();
        const uint32_t stb = sb + OFF_STAGE + (s & 3) * STAGE_SZ;
        const uint32_t sA = stb, sB = stb + A_SMEM;

        // ---- load + split A fragments for both m-tiles ----
        uint32_t AH[2][2][4], AL[2][2][4];          // [mt][ksub][frag]
#pragma unroll
        for (int mt = 0; mt < 2; mt++) {
            const int r0 = (wm * 2 + mt) * 16 + fr;
#pragma unroll
            for (int ks = 0; ks < 2; ks++) {
#pragma unroll
                for (int j = 0; j < 4; j++) {
                    int rr = r0 + (j & 1) * 8;
                    int kk = ks * 8 + fc + (j >> 1) * 4;
                    float x = lds_f32(sA + (uint32_t)(rr * A_PITCH_W + kk) * 4);
                    uint32_t h = f2tf32(x);
                    AH[mt][ks][j] = h;
                    AL[mt][ks][j] = f2tf32(x - __uint_as_float(h));
                }
            }
        }

        // ---- N tiles ----
#pragma unroll
        for (int nt = 0; nt < 8; nt++) {
            const int n = (wn * 8 + nt) * 8 + fr;
            uint32_t b0h[2], b0l[2], b1h[2], b1l[2];
#pragma unroll
            for (int ks = 0; ks < 2; ks++) {
                uint32_t base = sB + (uint32_t)(n * B_PITCH_W
                                              + (ks * 8 + fc) * 2) * 4;
                lds_v2(base,      b0h[ks], b0l[ks]);
                lds_v2(base + 32, b1h[ks], b1l[ks]);
            }
#pragma unroll
            for (int mt = 0; mt < 2; mt++) {
                float tm[4], tc[4];
                mma_zro(tm, AH[mt][0], b0h[0], b1h[0]);   // hi*wh k0 (c=0)
                mma_acc(tm, AH[mt][1], b0h[1], b1h[1]);   // hi*wh k1
                mma_zro(tc, AH[mt][0], b0l[0], b1l[0]);   // hi*wl (c=0)
                mma_acc(tc, AL[mt][0], b0h[0], b1h[0]);   // lo*wh
                mma_acc(tc, AH[mt][1], b0l[1], b1l[1]);   // hi*wl
                mma_acc(tc, AL[mt][1], b0h[1], b1h[1]);   // lo*wh
                acc[mt][nt][0] += tm[0] + tc[0];
                acc[mt][nt][1] += tm[1] + tc[1];
                acc[mt][nt][2] += tm[2] + tc[2];
                acc[mt][nt][3] += tm[3] + tc[3];
            }
        }

        if (s + 3 < NS) ISSUE(s + 3);
        asm volatile("cp.async.commit_group;" ::: "memory");
    }
#undef ISSUE

    __syncthreads();   // all warps done reading stage bufs

    // ---------------- dump logits to smem scores --------------------------
    {
        float* sc = (float*)(sm + OFF_STAGE);
#pragma unroll
        for (int mt = 0; mt < 2; mt++) {
            int r = wm * 32 + mt * 16 + fr;
#pragma unroll
            for (int nt = 0; nt < 8; nt++) {
                int c = wn * 64 + nt * 8 + fc * 2;
                sc[r * 257 + c]           = acc[mt][nt][0];
                sc[r * 257 + c + 1]       = acc[mt][nt][1];
                sc[(r + 8) * 257 + c]     = acc[mt][nt][2];
                sc[(r + 8) * 257 + c + 1] = acc[mt][nt][3];
            }
        }
    }
    __syncthreads();

    // ---------------- fused gating (warps 0-3, one token per thread) ------
    if (wid < 4) {
        const int row = wid * 32 + lane;
        float* srow = (float*)(sm + OFF_STAGE) + row * 257;
        const float* bs = (const float*)(sm + OFF_BIAS);

        float gs[8];
#pragma unroll
        for (int g = 0; g < 8; g++) {
            float m1 = -1e30f, m2 = -1e30f;
#pragma unroll
            for (int i = 0; i < 32; i++) {
                float lg = srow[g * 32 + i];
                float scv = 1.0f / (1.0f + expf(-lg));   // sigmoid
                float v = scv + bs[g * 32 + i];          // scores_for_choice
                srow[g * 32 + i] = v;
                if (v > m1) { m2 = m1; m1 = v; }
                else if (v > m2) m2 = v;
            }
            gs[g] = m1 + m2;
        }
        // stable top-4 groups (ties -> lower index)
        int mask = 0;
#pragma unroll
        for (int j = 0; j < 8; j++) {
            int rk = 0;
#pragma unroll
            for (int j2 = 0; j2 < 8; j2++)
                rk += (gs[j2] > gs[j]) || (gs[j2] == gs[j] && j2 < j);
            if (rk < 4) mask |= 1 << j;
        }
        // stable top-8 experts over masked scores (matches lax.top_k ties)
        float bv[8]; int bi[8];
#pragma unroll
        for (int k = 0; k < 8; k++) { bv[k] = -1e30f; bi[k] = 0; }
        for (int e = 0; e < NE; e++) {
            float v = ((mask >> (e >> 5)) & 1) ? srow[e] : 0.0f;
            if (v > bv[7]) {
                bv[7] = v; bi[7] = e;
#pragma unroll
                for (int k = 7; k > 0; k--)
                    if (bv[k] > bv[k - 1]) {
                        float tv = bv[k]; bv[k] = bv[k - 1]; bv[k - 1] = tv;
                        int ti = bi[k];  bi[k] = bi[k - 1]; bi[k - 1] = ti;
                    }
            }
        }
        float ws = 0.0f, wv[8];
#pragma unroll
        for (int k = 0; k < 8; k++) { wv[k] = bv[k] - bs[bi[k]]; ws += wv[k]; }
        const size_t token = (size_t)(m0 + row);
#pragma unroll
        for (int k = 0; k < 8; k++) {
            out[token * 8 + k] = (float)bi[k];
            out[(size_t)T * 8 + token * 8 + k] = wv[k] / (ws + 1e-20f) * 2.5f;
        }
    }
}

extern "C" void kernel_launch(void* const* d_in, const int* in_sizes, int n_in,
                              void* d_out, int out_size)
{
    const float* X    = (const float*)d_in[0];
    const float* W    = (const float*)d_in[1];
    const float* bias = (const float*)d_in[2];
    float* out = (float*)d_out;

    const int T = in_sizes[0] / KD;   // 16384

    wsplit_kernel<<<(NE * KD) / 256, 256>>>(W);

    cudaFuncSetAttribute(moe_kernel,
                         cudaFuncAttributeMaxDynamicSharedMemorySize, SMEM_TOTAL);
    moe_kernel<<<T / BM, 512, SMEM_TOTAL>>>(X, bias, out, T);
}